// round 1
// baseline (speedup 1.0000x reference)
#include <cuda_runtime.h>

#define DIM 32768
#define NTOK 32
#define NPQC 60

// Gate descriptor: p = param index, tgt = local slot of target bit,
// ctrl: 255 = none (RY), 0..11 = local slot, 16+o = outer (chunk) bit o.
struct G { unsigned char p, tgt, ctrl; };

// Pass 1: outer bits {12,13,14}, local slots = bits 0..11 (identity)
__constant__ G c_gP1[12] = {
  {3,11,255},{4,10,255},{5,9,255},{6,8,255},{7,7,255},{8,6,255},
  {9,5,255},{10,4,255},{11,3,255},{12,2,255},{13,1,255},{14,0,255}
};
// Pass 2: outer {9,10,11}; slots: b0-8->0-8, b12->9, b13->10, b14->11
__constant__ G c_gP2[13] = {
  {2,9,255},{1,10,255},{0,11,255},
  {15,11,0},{16,0,1},{17,1,2},{18,2,3},{19,3,4},{20,4,5},
  {21,5,6},{22,6,7},{23,7,8},{24,8,16}
};
// Pass 3: outer {5,6,7}; slots: b0-4->0-4, b8->5 ... b14->11
__constant__ G c_gP3[25] = {
  {25,6,7},{26,7,8},{27,8,9},{28,9,10},{29,10,11},
  {30,11,255},{31,10,255},{32,9,255},{33,8,255},{34,7,255},{35,6,255},{36,5,255},
  {40,4,255},{41,3,255},{42,2,255},{43,1,255},{44,0,255},
  {45,1,0},{46,0,11},{47,11,10},{48,10,9},{49,9,8},{50,8,7},{51,7,6},{52,6,5}
};
// Pass 4: outer {12,13,14}, identity slots
__constant__ G c_gP4[10] = {
  {37,7,255},{38,6,255},{39,5,255},
  {53,8,7},{54,7,6},{55,6,5},{56,5,4},{57,4,3},{58,3,2},{59,2,1}
};

__device__ float2 g_cs[NTOK * NPQC];   // cos/sin(theta/2) per token,param
__device__ float2 g_cs_ff[NPQC];       // final-evolve cos/sin
__device__ float2 g_lcu[NTOK];         // normalized LCU coefficients
__device__ float2 g_tok[NTOK * DIM];   // per-token evolving states (8 MB)
__device__ float2 g_m1[DIM];
__device__ float2 g_m2[DIM];
__device__ float2 g_acc[DIM];

// ---------------------------------------------------------------- setup ----
__global__ void setup_kernel(const float* __restrict__ emb,
                             const float* __restrict__ W,
                             const float* __restrict__ bias,
                             const float* __restrict__ lcu_ri,
                             const float* __restrict__ ffp) {
    int bx = blockIdx.x;
    if (bx < NTOK * NPQC) {
        int t = bx / NPQC, j = bx % NPQC;
        const float* e = emb + t * 1024;
        const float* w = W + j * 1024;
        float p = 0.f;
        for (int k = threadIdx.x; k < 1024; k += 128) p += e[k] * w[k];
        __shared__ float red[128];
        red[threadIdx.x] = p;
        __syncthreads();
        for (int s = 64; s > 0; s >>= 1) {
            if (threadIdx.x < s) red[threadIdx.x] += red[threadIdx.x + s];
            __syncthreads();
        }
        if (threadIdx.x == 0) {
            float h = 0.5f * (red[0] + bias[j]);
            g_cs[t * NPQC + j] = make_float2(cosf(h), sinf(h));
        }
    } else if (bx == NTOK * NPQC) {
        int j = threadIdx.x;
        if (j < NPQC) {
            float h = 0.5f * ffp[j];
            g_cs_ff[j] = make_float2(cosf(h), sinf(h));
        }
    } else {
        // LCU normalization (warp 0 only)
        if (threadIdx.x < 32) {
            int t = threadIdx.x;
            float re = lcu_ri[2 * t], im = lcu_ri[2 * t + 1];
            float mag = sqrtf(re * re + im * im);
            float s = mag;
            #pragma unroll
            for (int o = 16; o > 0; o >>= 1) s += __shfl_xor_sync(0xffffffffu, s, o);
            s = fmaxf(s, 1e-8f);
            g_lcu[t] = make_float2(re / s, im / s);
        }
    }
}

// ------------------------------------------------------------ pass kernel ----
template <int PASS>
__device__ __forceinline__ int amap(int c, int j) {
    if (PASS == 1 || PASS == 4) return j | (c << 12);
    if (PASS == 2) return (j & 511) | (c << 9) | ((j >> 9) << 12);
    return (j & 31) | (c << 5) | ((j >> 5) << 8);  // PASS 3
}

// srcsel: 0 = e0 basis state, 1 = g_tok (self, per token), 2 = g_m1,
//         3 = g_m2, 4 = g_acc.  use_ff: 1 -> ff cos/sin table.
template <int PASS, int NG>
__global__ void pass_kernel(int srcsel, int use_ff) {
    __shared__ float2 s[4096];
    int c = blockIdx.x;
    int t = blockIdx.y;
    const float2* cs = use_ff ? g_cs_ff : (g_cs + t * NPQC);
    const G* gs = (PASS == 1) ? c_gP1 : (PASS == 2) ? c_gP2 : (PASS == 3) ? c_gP3 : c_gP4;
    float2* dp = g_tok + (size_t)t * DIM;

    if (srcsel == 0) {
        for (int j = threadIdx.x; j < 4096; j += 256) {
            int i = amap<PASS>(c, j);
            s[j] = make_float2(i == 0 ? 1.f : 0.f, 0.f);
        }
    } else {
        const float2* sp = (srcsel == 1) ? dp : (srcsel == 2) ? g_m1
                         : (srcsel == 3) ? g_m2 : g_acc;
        for (int j = threadIdx.x; j < 4096; j += 256)
            s[j] = sp[amap<PASS>(c, j)];
    }

    #pragma unroll 1
    for (int g = 0; g < NG; ++g) {
        __syncthreads();
        G gg = gs[g];
        float2 csv = cs[gg.p];
        float cc = csv.x, ss = csv.y;
        int k = gg.tgt;
        int lowmask = (1 << k) - 1;
        bool isRY = (gg.ctrl == 255);
        int cm = -1;
        if (!isRY) {
            if (gg.ctrl >= 16) {
                if (!((c >> (gg.ctrl - 16)) & 1)) continue;  // uniform skip
            } else {
                cm = gg.ctrl;
            }
        }
        #pragma unroll
        for (int r = 0; r < 8; ++r) {
            int pidx = threadIdx.x + (r << 8);
            int j0 = ((pidx >> k) << (k + 1)) | (pidx & lowmask);
            int j1 = j0 | (1 << k);
            if (cm >= 0 && !((j0 >> cm) & 1)) continue;
            float2 a0 = s[j0], a1 = s[j1];
            if (isRY) {
                s[j0] = make_float2(cc * a0.x - ss * a1.x, cc * a0.y - ss * a1.y);
                s[j1] = make_float2(ss * a0.x + cc * a1.x, ss * a0.y + cc * a1.y);
            } else {  // controlled-RX on target (ctrl bit already checked)
                s[j0] = make_float2(cc * a0.x + ss * a1.y, cc * a0.y - ss * a1.x);
                s[j1] = make_float2(cc * a1.x + ss * a0.y, cc * a1.y - ss * a0.x);
            }
        }
    }
    __syncthreads();
    for (int j = threadIdx.x; j < 4096; j += 256)
        dp[amap<PASS>(c, j)] = s[j];
}

// ---------------------------------------------------------------- reduce ----
// out_sel: 1 -> g_m1, 2 -> g_m2, 3 -> g_acc (with qsvt combine)
__global__ void reduce_kernel(int out_sel, const float* __restrict__ qsvt) {
    int i = blockIdx.x * blockDim.x + threadIdx.x;
    float2 a = make_float2(0.f, 0.f);
    #pragma unroll
    for (int t = 0; t < NTOK; ++t) {
        float2 l = g_lcu[t];
        float2 v = g_tok[t * DIM + i];
        a.x += v.x * l.x - v.y * l.y;
        a.y += v.x * l.y + v.y * l.x;
    }
    if (out_sel == 1) {
        g_m1[i] = a;
    } else if (out_sel == 2) {
        g_m2[i] = a;
    } else {
        float q0 = qsvt[0], q1 = qsvt[1], q2 = qsvt[2], q3 = qsvt[3];
        float2 b1 = g_m1[i], b2 = g_m2[i];
        float2 o;
        o.x = q1 * b1.x + q2 * b2.x + q3 * a.x + (i == 0 ? q0 : 0.f);
        o.y = q1 * b1.y + q2 * b2.y + q3 * a.y;
        g_acc[i] = o;
    }
}

// --------------------------------------------------------------- measure ----
__global__ void measure_kernel(float* __restrict__ out) {
    const float2* st = g_tok;  // final state lives in token-0 slot
    int b = blockIdx.x;        // bit index 0..14 ; qubit w = 14 - b
    int tid = threadIdx.x;
    int lowmask = (1 << b) - 1;
    float x = 0.f, y = 0.f, z = 0.f, n = 0.f;
    for (int p = tid; p < DIM / 2; p += 256) {
        int i0 = ((p >> b) << (b + 1)) | (p & lowmask);
        int i1 = i0 | (1 << b);
        float2 a0 = st[i0], a1 = st[i1];
        x += a0.x * a1.x + a0.y * a1.y;          // Re(conj(a0)*a1)
        y += a0.x * a1.y - a0.y * a1.x;          // Im(conj(a0)*a1)
        float m0 = a0.x * a0.x + a0.y * a0.y;
        float m1 = a1.x * a1.x + a1.y * a1.y;
        z += m0 - m1;
        n += m0 + m1;
    }
    __shared__ float red[4 * 256];
    red[tid] = x; red[256 + tid] = y; red[512 + tid] = z; red[768 + tid] = n;
    __syncthreads();
    for (int s = 128; s > 0; s >>= 1) {
        if (tid < s) {
            red[tid]       += red[tid + s];
            red[256 + tid] += red[256 + tid + s];
            red[512 + tid] += red[512 + tid + s];
            red[768 + tid] += red[768 + tid + s];
        }
        __syncthreads();
    }
    if (tid == 0) {
        float inv = 1.f / fmaxf(red[768], 1e-20f);
        int w = 14 - b;
        out[w]      = 2.f * red[0]   * inv;   // X
        out[15 + w] = 2.f * red[256] * inv;   // Y
        out[30 + w] = red[512] * inv;         // Z
    }
}

// ---------------------------------------------------------------- launch ----
extern "C" void kernel_launch(void* const* d_in, const int* in_sizes, int n_in,
                              void* d_out, int out_size) {
    (void)in_sizes; (void)n_in; (void)out_size;
    const float* emb  = (const float*)d_in[0];
    const float* W    = (const float*)d_in[1];
    const float* bias = (const float*)d_in[2];
    const float* qsvt = (const float*)d_in[3];
    const float* lcu  = (const float*)d_in[4];
    const float* ffp  = (const float*)d_in[5];
    float* out = (float*)d_out;

    setup_kernel<<<NTOK * NPQC + 2, 128>>>(emb, W, bias, lcu, ffp);

    dim3 gs(8, NTOK);   // 8 chunks x 32 tokens
    dim3 gf(8, 1);      // final evolve: single state

    // stage 1 (input = e0)
    pass_kernel<1, 12><<<gs, 256>>>(0, 0);
    pass_kernel<2, 13><<<gs, 256>>>(1, 0);
    pass_kernel<3, 25><<<gs, 256>>>(1, 0);
    pass_kernel<4, 10><<<gs, 256>>>(1, 0);
    reduce_kernel<<<DIM / 256, 256>>>(1, nullptr);

    // stage 2 (input = m1)
    pass_kernel<1, 12><<<gs, 256>>>(2, 0);
    pass_kernel<2, 13><<<gs, 256>>>(1, 0);
    pass_kernel<3, 25><<<gs, 256>>>(1, 0);
    pass_kernel<4, 10><<<gs, 256>>>(1, 0);
    reduce_kernel<<<DIM / 256, 256>>>(2, nullptr);

    // stage 3 (input = m2) + qsvt combine -> acc
    pass_kernel<1, 12><<<gs, 256>>>(3, 0);
    pass_kernel<2, 13><<<gs, 256>>>(1, 0);
    pass_kernel<3, 25><<<gs, 256>>>(1, 0);
    pass_kernel<4, 10><<<gs, 256>>>(1, 0);
    reduce_kernel<<<DIM / 256, 256>>>(3, qsvt);

    // final evolve on acc (ff params), result lands in g_tok[0..DIM)
    pass_kernel<1, 12><<<gf, 256>>>(4, 1);
    pass_kernel<2, 13><<<gf, 256>>>(1, 1);
    pass_kernel<3, 25><<<gf, 256>>>(1, 1);
    pass_kernel<4, 10><<<gf, 256>>>(1, 1);

    measure_kernel<<<15, 256>>>(out);
}

// round 3
// speedup vs baseline: 1.2540x; 1.2540x over previous
#include <cuda_runtime.h>

#define DIM 32768
#define NTOK 32
#define NPQC 60

// Gate descriptor: p = param index, tgt = local slot of target bit,
// ctrl: 255 = none (RY), 0..11 = local slot, 16+o = outer (chunk) bit o.
struct G { unsigned char p, tgt, ctrl; };

// Flattened per-pass gate tables, grouped into contiguous "rounds" whose
// targets all fall inside a 4-slot group (register-blocked application).
__constant__ G c_g1[12] = {
  {3,11,255},{4,10,255},{5,9,255},{6,8,255},        // round mask 0xF00
  {7,7,255},{8,6,255},{9,5,255},{10,4,255},         // round mask 0x0F0
  {11,3,255},{12,2,255},{13,1,255},{14,0,255}       // round mask 0x00F
};
__constant__ G c_g2[13] = {
  {2,9,255},{1,10,255},{0,11,255},                  // 0xF00
  {15,11,0},{16,0,1},{17,1,2},{18,2,3},             // 0x807
  {19,3,4},{20,4,5},{21,5,6},{22,6,7},              // 0x078
  {23,7,8},{24,8,16}                                // 0x780
};
__constant__ G c_g3[25] = {
  {25,6,7},{26,7,8},{27,8,9},{28,9,10},             // 0x3C0
  {29,10,11},{30,11,255},{31,10,255},{32,9,255},{33,8,255}, // 0xF00
  {34,7,255},{35,6,255},{36,5,255},{40,4,255},      // 0x0F0
  {41,3,255},{42,2,255},{43,1,255},{44,0,255},{45,1,0},     // 0x00F
  {46,0,11},{47,11,10},{48,10,9},{49,9,8},          // 0xE01
  {50,8,7},{51,7,6},{52,6,5}                        // 0x1E0
};
__constant__ G c_g4[10] = {
  {37,7,255},{38,6,255},{39,5,255},
  {53,8,7},{54,7,6},{55,6,5},{56,5,4},              // 0x1E0 (7 gates)
  {57,4,3},{58,3,2},{59,2,1}                        // 0x01E
};

__device__ float2 g_cs[NTOK * NPQC];   // cos/sin(theta/2) per token,param
__device__ float2 g_cs_ff[NPQC];       // final-evolve cos/sin
__device__ float2 g_lcu[NTOK];         // normalized LCU coefficients
__device__ float2 g_tok[NTOK * DIM];   // per-token evolving states (8 MB)
__device__ float2 g_m1[DIM];
__device__ float2 g_m2[DIM];
__device__ float2 g_acc[DIM];

// ---------------------------------------------------------------- setup ----
__global__ void setup_kernel(const float* __restrict__ emb,
                             const float* __restrict__ W,
                             const float* __restrict__ bias,
                             const float* __restrict__ lcu_ri,
                             const float* __restrict__ ffp) {
    int bx = blockIdx.x;
    if (bx < NTOK * NPQC) {
        int t = bx / NPQC, j = bx % NPQC;
        const float* e = emb + t * 1024;
        const float* w = W + j * 1024;
        float p = 0.f;
        for (int k = threadIdx.x; k < 1024; k += 128) p += e[k] * w[k];
        __shared__ float red[128];
        red[threadIdx.x] = p;
        __syncthreads();
        for (int s = 64; s > 0; s >>= 1) {
            if (threadIdx.x < s) red[threadIdx.x] += red[threadIdx.x + s];
            __syncthreads();
        }
        if (threadIdx.x == 0) {
            float h = 0.5f * (red[0] + bias[j]);
            g_cs[t * NPQC + j] = make_float2(cosf(h), sinf(h));
        }
    } else if (bx == NTOK * NPQC) {
        int j = threadIdx.x;
        if (j < NPQC) {
            float h = 0.5f * ffp[j];
            g_cs_ff[j] = make_float2(cosf(h), sinf(h));
        }
    } else {
        if (threadIdx.x < 32) {
            int t = threadIdx.x;
            float re = lcu_ri[2 * t], im = lcu_ri[2 * t + 1];
            float mag = sqrtf(re * re + im * im);
            float s = mag;
            #pragma unroll
            for (int o = 16; o > 0; o >>= 1) s += __shfl_xor_sync(0xffffffffu, s, o);
            s = fmaxf(s, 1e-8f);
            g_lcu[t] = make_float2(re / s, im / s);
        }
    }
}

// ------------------------------------------------------------ pass kernel ----
template <int PASS>
__device__ __forceinline__ int amap(int c, int j) {
    if (PASS == 1 || PASS == 4) return j | (c << 12);
    if (PASS == 2) return (j & 511) | (c << 9) | ((j >> 9) << 12);
    return (j & 31) | (c << 5) | ((j >> 5) << 8);  // PASS 3
}

// Bank-conflict-avoiding swizzle (bijective on 12-bit index).
__device__ __forceinline__ int swz(int j) {
    return j ^ ((j >> 4) & 15) ^ ((j >> 8) & 15);
}

template <int GMASK>
struct GroupInfo {
    __host__ __device__ static constexpr int slot(int n) {
        int c = 0;
        for (int s = 0; s < 12; ++s)
            if (GMASK & (1 << s)) { if (c == n) return s; ++c; }
        return 0;
    }
};

// Apply one gate whose target is group-position Q on the 16 register amps.
template <int Q>
__device__ __forceinline__ void apply_gate_q(float2* a, float cc, float ss,
                                             bool isRY, int cpos) {
    #pragma unroll
    for (int m = 0; m < 8; ++m) {
        int i0 = ((m >> Q) << (Q + 1)) | (m & ((1 << Q) - 1));
        int i1 = i0 | (1 << Q);
        if (cpos >= 0 && !((i0 >> cpos) & 1)) continue;
        float2 a0 = a[i0], a1 = a[i1];
        if (isRY) {
            a[i0] = make_float2(cc * a0.x - ss * a1.x, cc * a0.y - ss * a1.y);
            a[i1] = make_float2(ss * a0.x + cc * a1.x, ss * a0.y + cc * a1.y);
        } else {
            a[i0] = make_float2(cc * a0.x + ss * a1.y, cc * a0.y - ss * a1.x);
            a[i1] = make_float2(cc * a1.x + ss * a0.y, cc * a1.y - ss * a0.x);
        }
    }
}

// One round: gather 16 amps (4 group bits), apply ng gates, scatter, sync.
template <int GMASK>
__device__ __forceinline__ void do_round(float2* s, const float2* __restrict__ cs,
                                         const G* gs, int ng, int c) {
    constexpr int S0 = GroupInfo<GMASK>::slot(0);
    constexpr int S1 = GroupInfo<GMASK>::slot(1);
    constexpr int S2 = GroupInfo<GMASK>::slot(2);
    constexpr int S3 = GroupInfo<GMASK>::slot(3);

    int base = 0;
    {
        int t = threadIdx.x;
        #pragma unroll
        for (int sl = 0; sl < 12; ++sl)
            if (!(GMASK & (1 << sl))) { base |= (t & 1) << sl; t >>= 1; }
    }

    float2 a[16];
    #pragma unroll
    for (int m = 0; m < 16; ++m) {
        int idx = base | ((m & 1) << S0) | (((m >> 1) & 1) << S1)
                       | (((m >> 2) & 1) << S2) | (((m >> 3) & 1) << S3);
        a[m] = s[swz(idx)];
    }

    for (int g = 0; g < ng; ++g) {
        G gg = gs[g];
        float2 v = cs[gg.p];
        bool isRY = (gg.ctrl == 255);
        bool on = true;
        int cpos = -1;
        if (!isRY) {
            if (gg.ctrl >= 16) {
                on = (c >> (gg.ctrl - 16)) & 1;
            } else if (GMASK & (1 << gg.ctrl)) {
                cpos = (gg.ctrl == S0) ? 0 : (gg.ctrl == S1) ? 1
                     : (gg.ctrl == S2) ? 2 : 3;
            } else {
                on = (base >> gg.ctrl) & 1;
            }
        }
        if (on) {
            int tq = (gg.tgt == S0) ? 0 : (gg.tgt == S1) ? 1
                   : (gg.tgt == S2) ? 2 : 3;
            switch (tq) {
                case 0: apply_gate_q<0>(a, v.x, v.y, isRY, cpos); break;
                case 1: apply_gate_q<1>(a, v.x, v.y, isRY, cpos); break;
                case 2: apply_gate_q<2>(a, v.x, v.y, isRY, cpos); break;
                default: apply_gate_q<3>(a, v.x, v.y, isRY, cpos); break;
            }
        }
    }

    #pragma unroll
    for (int m = 0; m < 16; ++m) {
        int idx = base | ((m & 1) << S0) | (((m >> 1) & 1) << S1)
                       | (((m >> 2) & 1) << S2) | (((m >> 3) & 1) << S3);
        s[swz(idx)] = a[m];
    }
    __syncthreads();
}

// srcsel: 0 = e0 basis state, 1 = g_tok (self, per token), 2 = g_m1,
//         3 = g_m2, 4 = g_acc.  use_ff: 1 -> ff cos/sin table.
template <int PASS>
__global__ void __launch_bounds__(256) pass_kernel(int srcsel, int use_ff) {
    __shared__ float2 s[4096];
    int c = blockIdx.x;
    int t = blockIdx.y;
    const float2* cs = use_ff ? g_cs_ff : (g_cs + t * NPQC);
    float2* dp = g_tok + (size_t)t * DIM;

    if (srcsel == 0) {
        for (int j = threadIdx.x; j < 4096; j += 256) {
            int i = amap<PASS>(c, j);
            s[swz(j)] = make_float2(i == 0 ? 1.f : 0.f, 0.f);
        }
    } else {
        const float2* sp = (srcsel == 1) ? dp : (srcsel == 2) ? g_m1
                         : (srcsel == 3) ? g_m2 : g_acc;
        for (int j = threadIdx.x; j < 4096; j += 256)
            s[swz(j)] = sp[amap<PASS>(c, j)];
    }
    __syncthreads();

    if (PASS == 1) {
        do_round<0xF00>(s, cs, c_g1 + 0, 4, c);
        do_round<0x0F0>(s, cs, c_g1 + 4, 4, c);
        do_round<0x00F>(s, cs, c_g1 + 8, 4, c);
    } else if (PASS == 2) {
        do_round<0xF00>(s, cs, c_g2 + 0, 3, c);
        do_round<0x807>(s, cs, c_g2 + 3, 4, c);
        do_round<0x078>(s, cs, c_g2 + 7, 4, c);
        do_round<0x780>(s, cs, c_g2 + 11, 2, c);
    } else if (PASS == 3) {
        do_round<0x3C0>(s, cs, c_g3 + 0, 4, c);
        do_round<0xF00>(s, cs, c_g3 + 4, 5, c);
        do_round<0x0F0>(s, cs, c_g3 + 9, 4, c);
        do_round<0x00F>(s, cs, c_g3 + 13, 5, c);
        do_round<0xE01>(s, cs, c_g3 + 18, 4, c);
        do_round<0x1E0>(s, cs, c_g3 + 22, 3, c);
    } else {
        do_round<0x1E0>(s, cs, c_g4 + 0, 7, c);
        do_round<0x01E>(s, cs, c_g4 + 7, 3, c);
    }

    for (int j = threadIdx.x; j < 4096; j += 256)
        dp[amap<PASS>(c, j)] = s[swz(j)];
}

// ---------------------------------------------------------------- reduce ----
__global__ void reduce_kernel(int out_sel, const float* __restrict__ qsvt) {
    int i = blockIdx.x * blockDim.x + threadIdx.x;
    float2 a = make_float2(0.f, 0.f);
    #pragma unroll
    for (int t = 0; t < NTOK; ++t) {
        float2 l = g_lcu[t];
        float2 v = g_tok[t * DIM + i];
        a.x += v.x * l.x - v.y * l.y;
        a.y += v.x * l.y + v.y * l.x;
    }
    if (out_sel == 1) {
        g_m1[i] = a;
    } else if (out_sel == 2) {
        g_m2[i] = a;
    } else {
        float q0 = qsvt[0], q1 = qsvt[1], q2 = qsvt[2], q3 = qsvt[3];
        float2 b1 = g_m1[i], b2 = g_m2[i];
        float2 o;
        o.x = q1 * b1.x + q2 * b2.x + q3 * a.x + (i == 0 ? q0 : 0.f);
        o.y = q1 * b1.y + q2 * b2.y + q3 * a.y;
        g_acc[i] = o;
    }
}

// --------------------------------------------------------------- measure ----
__global__ void measure_kernel(float* __restrict__ out) {
    const float2* st = g_tok;  // final state lives in token-0 slot
    int b = blockIdx.x;        // bit index 0..14 ; qubit w = 14 - b
    int tid = threadIdx.x;
    int lowmask = (1 << b) - 1;
    float x = 0.f, y = 0.f, z = 0.f, n = 0.f;
    for (int p = tid; p < DIM / 2; p += 256) {
        int i0 = ((p >> b) << (b + 1)) | (p & lowmask);
        int i1 = i0 | (1 << b);
        float2 a0 = st[i0], a1 = st[i1];
        x += a0.x * a1.x + a0.y * a1.y;
        y += a0.x * a1.y - a0.y * a1.x;
        float m0 = a0.x * a0.x + a0.y * a0.y;
        float m1 = a1.x * a1.x + a1.y * a1.y;
        z += m0 - m1;
        n += m0 + m1;
    }
    __shared__ float red[4 * 256];
    red[tid] = x; red[256 + tid] = y; red[512 + tid] = z; red[768 + tid] = n;
    __syncthreads();
    for (int s = 128; s > 0; s >>= 1) {
        if (tid < s) {
            red[tid]       += red[tid + s];
            red[256 + tid] += red[256 + tid + s];
            red[512 + tid] += red[512 + tid + s];
            red[768 + tid] += red[768 + tid + s];
        }
        __syncthreads();
    }
    if (tid == 0) {
        float inv = 1.f / fmaxf(red[768], 1e-20f);
        int w = 14 - b;
        out[w]      = 2.f * red[0]   * inv;
        out[15 + w] = 2.f * red[256] * inv;
        out[30 + w] = red[512] * inv;
    }
}

// ---------------------------------------------------------------- launch ----
extern "C" void kernel_launch(void* const* d_in, const int* in_sizes, int n_in,
                              void* d_out, int out_size) {
    (void)in_sizes; (void)n_in; (void)out_size;
    const float* emb  = (const float*)d_in[0];
    const float* W    = (const float*)d_in[1];
    const float* bias = (const float*)d_in[2];
    const float* qsvt = (const float*)d_in[3];
    const float* lcu  = (const float*)d_in[4];
    const float* ffp  = (const float*)d_in[5];
    float* out = (float*)d_out;

    setup_kernel<<<NTOK * NPQC + 2, 128>>>(emb, W, bias, lcu, ffp);

    dim3 gs(8, NTOK);   // 8 chunks x 32 tokens
    dim3 gf(8, 1);      // final evolve: single state

    // stage 1 (input = e0)
    pass_kernel<1><<<gs, 256>>>(0, 0);
    pass_kernel<2><<<gs, 256>>>(1, 0);
    pass_kernel<3><<<gs, 256>>>(1, 0);
    pass_kernel<4><<<gs, 256>>>(1, 0);
    reduce_kernel<<<DIM / 256, 256>>>(1, nullptr);

    // stage 2 (input = m1)
    pass_kernel<1><<<gs, 256>>>(2, 0);
    pass_kernel<2><<<gs, 256>>>(1, 0);
    pass_kernel<3><<<gs, 256>>>(1, 0);
    pass_kernel<4><<<gs, 256>>>(1, 0);
    reduce_kernel<<<DIM / 256, 256>>>(2, nullptr);

    // stage 3 (input = m2) + qsvt combine -> acc
    pass_kernel<1><<<gs, 256>>>(3, 0);
    pass_kernel<2><<<gs, 256>>>(1, 0);
    pass_kernel<3><<<gs, 256>>>(1, 0);
    pass_kernel<4><<<gs, 256>>>(1, 0);
    reduce_kernel<<<DIM / 256, 256>>>(3, qsvt);

    // final evolve on acc (ff params), result lands in g_tok[0..DIM)
    pass_kernel<1><<<gf, 256>>>(4, 1);
    pass_kernel<2><<<gf, 256>>>(1, 1);
    pass_kernel<3><<<gf, 256>>>(1, 1);
    pass_kernel<4><<<gf, 256>>>(1, 1);

    measure_kernel<<<15, 256>>>(out);
}

// round 4
// speedup vs baseline: 2.4429x; 1.9481x over previous
#include <cuda_runtime.h>

#define DIM 32768
#define NTOK 32
#define NPQC 60

typedef unsigned long long ull;

// ----------------------------------------------------------- f32x2 helpers --
__device__ __forceinline__ ull f2_mul(ull a, ull b) {
    ull d; asm("mul.rn.f32x2 %0,%1,%2;" : "=l"(d) : "l"(a), "l"(b)); return d;
}
__device__ __forceinline__ ull f2_fma(ull a, ull b, ull c) {
    ull d; asm("fma.rn.f32x2 %0,%1,%2,%3;" : "=l"(d) : "l"(a), "l"(b), "l"(c)); return d;
}
__device__ __forceinline__ ull f2_pack(float x, float y) {
    ull d; asm("mov.b64 %0,{%1,%2};" : "=l"(d) : "f"(x), "f"(y)); return d;
}
__device__ __forceinline__ float2 f2_unpack(ull v) {
    float2 r; asm("mov.b64 {%0,%1},%2;" : "=f"(r.x), "=f"(r.y) : "l"(v)); return r;
}

// ------------------------------------------------------------- gate encode --
__host__ __device__ constexpr int RYg(int p, int t) { return p | (t << 8) | (255 << 16); }
__host__ __device__ constexpr int CXg(int p, int t, int c) { return p | (t << 8) | (c << 16); }

__host__ __device__ constexpr int swz_c(int j) {
    return j ^ ((j >> 4) & 15) ^ ((j >> 8) & 15);
}
__host__ __device__ constexpr int gslot(int gmask, int n) {
    int c = 0;
    for (int s = 0; s < 12; ++s)
        if (gmask & (1 << s)) { if (c == n) return s; ++c; }
    return 0;
}
__host__ __device__ constexpr int spread4(int gmask, int m) {
    return ((m & 1) << gslot(gmask, 0)) | (((m >> 1) & 1) << gslot(gmask, 1))
         | (((m >> 2) & 1) << gslot(gmask, 2)) | (((m >> 3) & 1) << gslot(gmask, 3));
}

__device__ float2 g_cs[NTOK * NPQC];
__device__ float2 g_cs_ff[NPQC];
__device__ float2 g_lcu[NTOK];
__device__ float2 g_tok[NTOK * DIM];
__device__ float2 g_m1[DIM];
__device__ float2 g_m2[DIM];
__device__ float2 g_acc[DIM];

// ---------------------------------------------------------------- setup ----
__global__ void setup_kernel(const float* __restrict__ emb,
                             const float* __restrict__ W,
                             const float* __restrict__ bias,
                             const float* __restrict__ lcu_ri,
                             const float* __restrict__ ffp) {
    int bx = blockIdx.x;
    if (bx < NTOK * NPQC) {
        int t = bx / NPQC, j = bx % NPQC;
        const float* e = emb + t * 1024;
        const float* w = W + j * 1024;
        float p = 0.f;
        for (int k = threadIdx.x; k < 1024; k += 128) p += e[k] * w[k];
        __shared__ float red[128];
        red[threadIdx.x] = p;
        __syncthreads();
        for (int s = 64; s > 0; s >>= 1) {
            if (threadIdx.x < s) red[threadIdx.x] += red[threadIdx.x + s];
            __syncthreads();
        }
        if (threadIdx.x == 0) {
            float h = 0.5f * (red[0] + bias[j]);
            g_cs[t * NPQC + j] = make_float2(cosf(h), sinf(h));
        }
    } else if (bx == NTOK * NPQC) {
        int j = threadIdx.x;
        if (j < NPQC) {
            float h = 0.5f * ffp[j];
            g_cs_ff[j] = make_float2(cosf(h), sinf(h));
        }
    } else {
        if (threadIdx.x < 32) {
            int t = threadIdx.x;
            float re = lcu_ri[2 * t], im = lcu_ri[2 * t + 1];
            float mag = sqrtf(re * re + im * im);
            float s = mag;
            #pragma unroll
            for (int o = 16; o > 0; o >>= 1) s += __shfl_xor_sync(0xffffffffu, s, o);
            s = fmaxf(s, 1e-8f);
            g_lcu[t] = make_float2(re / s, im / s);
        }
    }
}

// ------------------------------------------------------------ pass kernel ----
template <int PASS>
__device__ __forceinline__ int amap(int c, int j) {
    if (PASS == 1 || PASS == 4) return j | (c << 12);
    if (PASS == 2) return (j & 511) | (c << 9) | ((j >> 9) << 12);
    return (j & 31) | (c << 5) | ((j >> 5) << 8);  // PASS 3
}

// Apply one compile-time-encoded gate to the 16 register amps.
template <int GMASK, int ENC>
__device__ __forceinline__ void apply_one(ull* a, const float2* __restrict__ cs,
                                          int c, int base) {
    constexpr int P = ENC & 255;
    constexpr int TGT = (ENC >> 8) & 255;
    constexpr int CTRL = (ENC >> 16) & 255;
    constexpr int S0 = gslot(GMASK, 0), S1 = gslot(GMASK, 1);
    constexpr int S2 = gslot(GMASK, 2), S3 = gslot(GMASK, 3);
    constexpr int Q = (TGT == S0) ? 0 : (TGT == S1) ? 1 : (TGT == S2) ? 2 : 3;

    float2 v = cs[P];
    if constexpr (CTRL == 255) {  // RY, packed f32x2
        ull cc2 = f2_pack(v.x, v.x);
        ull ss2 = f2_pack(v.y, v.y);
        ull ns2 = f2_pack(-v.y, -v.y);
        #pragma unroll
        for (int m = 0; m < 8; ++m) {
            int i0 = ((m >> Q) << (Q + 1)) | (m & ((1 << Q) - 1));
            int i1 = i0 | (1 << Q);
            ull t0 = f2_fma(cc2, a[i0], f2_mul(ns2, a[i1]));
            a[i1]  = f2_fma(cc2, a[i1], f2_mul(ss2, a[i0]));
            a[i0]  = t0;
        }
    } else {  // controlled-RX
        constexpr bool inG = (CTRL < 16) && ((GMASK >> CTRL) & 1);
        constexpr int CPOS = inG ? ((CTRL == S0) ? 0 : (CTRL == S1) ? 1
                                  : (CTRL == S2) ? 2 : 3) : -1;
        bool on = true;
        if constexpr (CTRL >= 16) on = (c >> (CTRL - 16)) & 1;
        else if constexpr (!inG)  on = (base >> CTRL) & 1;
        if (on) {
            float cc = v.x, ss = v.y;
            #pragma unroll
            for (int m = 0; m < 8; ++m) {
                int i0 = ((m >> Q) << (Q + 1)) | (m & ((1 << Q) - 1));
                int i1 = i0 | (1 << Q);
                if (CPOS >= 0 && !((i0 >> CPOS) & 1)) continue;  // folds
                float2 a0 = f2_unpack(a[i0]), a1 = f2_unpack(a[i1]);
                float n0x = fmaf(cc, a0.x,  ss * a1.y);
                float n0y = fmaf(cc, a0.y, -ss * a1.x);
                float n1x = fmaf(cc, a1.x,  ss * a0.y);
                float n1y = fmaf(cc, a1.y, -ss * a0.x);
                a[i0] = f2_pack(n0x, n0y);
                a[i1] = f2_pack(n1x, n1y);
            }
        }
    }
}

// One round: gather 16 amps, apply gates (compile-time list), scatter, sync.
template <int GMASK, int... ENCS>
__device__ __forceinline__ void do_round(float2* s, const float2* __restrict__ cs,
                                         int c) {
    int base = 0;
    {
        int t = threadIdx.x;
        #pragma unroll
        for (int sl = 0; sl < 12; ++sl)
            if (!((GMASK >> sl) & 1)) { base |= (t & 1) << sl; t >>= 1; }
    }
    int sb = swz_c(base);
    ull* s64 = reinterpret_cast<ull*>(s);

    ull a[16];
    #pragma unroll
    for (int m = 0; m < 16; ++m)
        a[m] = s64[sb ^ swz_c(spread4(GMASK, m))];

    (apply_one<GMASK, ENCS>(a, cs, c, base), ...);

    #pragma unroll
    for (int m = 0; m < 16; ++m)
        s64[sb ^ swz_c(spread4(GMASK, m))] = a[m];
    __syncthreads();
}

// srcsel: 0 = e0 basis state, 1 = g_tok (self, per token), 2 = g_m1,
//         3 = g_m2, 4 = g_acc.  use_ff: 1 -> ff cos/sin table.
template <int PASS>
__global__ void __launch_bounds__(256) pass_kernel(int srcsel, int use_ff) {
    __shared__ float2 s[4096];
    int c = blockIdx.x;
    int t = blockIdx.y;
    const float2* cs = use_ff ? g_cs_ff : (g_cs + t * NPQC);
    float2* dp = g_tok + (size_t)t * DIM;

    if (srcsel == 0) {
        for (int j = threadIdx.x; j < 4096; j += 256) {
            int i = amap<PASS>(c, j);
            s[swz_c(j)] = make_float2(i == 0 ? 1.f : 0.f, 0.f);
        }
    } else {
        const float2* sp = (srcsel == 1) ? dp : (srcsel == 2) ? g_m1
                         : (srcsel == 3) ? g_m2 : g_acc;
        #pragma unroll 4
        for (int j = threadIdx.x; j < 4096; j += 256)
            s[swz_c(j)] = sp[amap<PASS>(c, j)];
    }
    __syncthreads();

    if constexpr (PASS == 1) {
        do_round<0xF00, RYg(3,11), RYg(4,10), RYg(5,9), RYg(6,8)>(s, cs, c);
        do_round<0x0F0, RYg(7,7), RYg(8,6), RYg(9,5), RYg(10,4)>(s, cs, c);
        do_round<0x00F, RYg(11,3), RYg(12,2), RYg(13,1), RYg(14,0)>(s, cs, c);
    } else if constexpr (PASS == 2) {
        do_round<0xF00, RYg(2,9), RYg(1,10), RYg(0,11)>(s, cs, c);
        do_round<0x807, CXg(15,11,0), CXg(16,0,1), CXg(17,1,2), CXg(18,2,3)>(s, cs, c);
        do_round<0x078, CXg(19,3,4), CXg(20,4,5), CXg(21,5,6), CXg(22,6,7)>(s, cs, c);
        do_round<0x780, CXg(23,7,8), CXg(24,8,16)>(s, cs, c);
    } else if constexpr (PASS == 3) {
        do_round<0x3C0, CXg(25,6,7), CXg(26,7,8), CXg(27,8,9), CXg(28,9,10)>(s, cs, c);
        do_round<0xF00, CXg(29,10,11), RYg(30,11), RYg(31,10), RYg(32,9), RYg(33,8)>(s, cs, c);
        do_round<0x0F0, RYg(34,7), RYg(35,6), RYg(36,5), RYg(40,4)>(s, cs, c);
        do_round<0x00F, RYg(41,3), RYg(42,2), RYg(43,1), RYg(44,0), CXg(45,1,0)>(s, cs, c);
        do_round<0xE01, CXg(46,0,11), CXg(47,11,10), CXg(48,10,9), CXg(49,9,8)>(s, cs, c);
        do_round<0x1E0, CXg(50,8,7), CXg(51,7,6), CXg(52,6,5)>(s, cs, c);
    } else {
        do_round<0x1E0, RYg(37,7), RYg(38,6), RYg(39,5),
                 CXg(53,8,7), CXg(54,7,6), CXg(55,6,5), CXg(56,5,4)>(s, cs, c);
        do_round<0x01E, CXg(57,4,3), CXg(58,3,2), CXg(59,2,1)>(s, cs, c);
    }

    #pragma unroll 4
    for (int j = threadIdx.x; j < 4096; j += 256)
        dp[amap<PASS>(c, j)] = s[swz_c(j)];
}

// ---------------------------------------------------------------- reduce ----
__global__ void reduce_kernel(int out_sel, const float* __restrict__ qsvt) {
    int i = blockIdx.x * blockDim.x + threadIdx.x;
    float2 a = make_float2(0.f, 0.f);
    #pragma unroll
    for (int t = 0; t < NTOK; ++t) {
        float2 l = g_lcu[t];
        float2 v = g_tok[t * DIM + i];
        a.x += v.x * l.x - v.y * l.y;
        a.y += v.x * l.y + v.y * l.x;
    }
    if (out_sel == 1) {
        g_m1[i] = a;
    } else if (out_sel == 2) {
        g_m2[i] = a;
    } else {
        float q0 = qsvt[0], q1 = qsvt[1], q2 = qsvt[2], q3 = qsvt[3];
        float2 b1 = g_m1[i], b2 = g_m2[i];
        float2 o;
        o.x = q1 * b1.x + q2 * b2.x + q3 * a.x + (i == 0 ? q0 : 0.f);
        o.y = q1 * b1.y + q2 * b2.y + q3 * a.y;
        g_acc[i] = o;
    }
}

// --------------------------------------------------------------- measure ----
__global__ void measure_kernel(float* __restrict__ out) {
    const float2* st = g_tok;  // final state lives in token-0 slot
    int b = blockIdx.x;        // bit index 0..14 ; qubit w = 14 - b
    int tid = threadIdx.x;
    int lowmask = (1 << b) - 1;
    float x = 0.f, y = 0.f, z = 0.f, n = 0.f;
    for (int p = tid; p < DIM / 2; p += 256) {
        int i0 = ((p >> b) << (b + 1)) | (p & lowmask);
        int i1 = i0 | (1 << b);
        float2 a0 = st[i0], a1 = st[i1];
        x += a0.x * a1.x + a0.y * a1.y;
        y += a0.x * a1.y - a0.y * a1.x;
        float m0 = a0.x * a0.x + a0.y * a0.y;
        float m1 = a1.x * a1.x + a1.y * a1.y;
        z += m0 - m1;
        n += m0 + m1;
    }
    __shared__ float red[4 * 256];
    red[tid] = x; red[256 + tid] = y; red[512 + tid] = z; red[768 + tid] = n;
    __syncthreads();
    for (int s = 128; s > 0; s >>= 1) {
        if (tid < s) {
            red[tid]       += red[tid + s];
            red[256 + tid] += red[256 + tid + s];
            red[512 + tid] += red[512 + tid + s];
            red[768 + tid] += red[768 + tid + s];
        }
        __syncthreads();
    }
    if (tid == 0) {
        float inv = 1.f / fmaxf(red[768], 1e-20f);
        int w = 14 - b;
        out[w]      = 2.f * red[0]   * inv;
        out[15 + w] = 2.f * red[256] * inv;
        out[30 + w] = red[512] * inv;
    }
}

// ---------------------------------------------------------------- launch ----
extern "C" void kernel_launch(void* const* d_in, const int* in_sizes, int n_in,
                              void* d_out, int out_size) {
    (void)in_sizes; (void)n_in; (void)out_size;
    const float* emb  = (const float*)d_in[0];
    const float* W    = (const float*)d_in[1];
    const float* bias = (const float*)d_in[2];
    const float* qsvt = (const float*)d_in[3];
    const float* lcu  = (const float*)d_in[4];
    const float* ffp  = (const float*)d_in[5];
    float* out = (float*)d_out;

    setup_kernel<<<NTOK * NPQC + 2, 128>>>(emb, W, bias, lcu, ffp);

    dim3 gs(8, NTOK);   // 8 chunks x 32 tokens
    dim3 gf(8, 1);      // final evolve: single state

    // stage 1 (input = e0)
    pass_kernel<1><<<gs, 256>>>(0, 0);
    pass_kernel<2><<<gs, 256>>>(1, 0);
    pass_kernel<3><<<gs, 256>>>(1, 0);
    pass_kernel<4><<<gs, 256>>>(1, 0);
    reduce_kernel<<<DIM / 256, 256>>>(1, nullptr);

    // stage 2 (input = m1)
    pass_kernel<1><<<gs, 256>>>(2, 0);
    pass_kernel<2><<<gs, 256>>>(1, 0);
    pass_kernel<3><<<gs, 256>>>(1, 0);
    pass_kernel<4><<<gs, 256>>>(1, 0);
    reduce_kernel<<<DIM / 256, 256>>>(2, nullptr);

    // stage 3 (input = m2) + qsvt combine -> acc
    pass_kernel<1><<<gs, 256>>>(3, 0);
    pass_kernel<2><<<gs, 256>>>(1, 0);
    pass_kernel<3><<<gs, 256>>>(1, 0);
    pass_kernel<4><<<gs, 256>>>(1, 0);
    reduce_kernel<<<DIM / 256, 256>>>(3, qsvt);

    // final evolve on acc (ff params), result lands in g_tok[0..DIM)
    pass_kernel<1><<<gf, 256>>>(4, 1);
    pass_kernel<2><<<gf, 256>>>(1, 1);
    pass_kernel<3><<<gf, 256>>>(1, 1);
    pass_kernel<4><<<gf, 256>>>(1, 1);

    measure_kernel<<<15, 256>>>(out);
}

// round 5
// speedup vs baseline: 2.5787x; 1.0556x over previous
#include <cuda_runtime.h>

#define DIM 32768
#define NTOK 32
#define NPQC 60

typedef unsigned long long ull;

// ----------------------------------------------------------- f32x2 helpers --
__device__ __forceinline__ ull f2_mul(ull a, ull b) {
    ull d; asm("mul.rn.f32x2 %0,%1,%2;" : "=l"(d) : "l"(a), "l"(b)); return d;
}
__device__ __forceinline__ ull f2_fma(ull a, ull b, ull c) {
    ull d; asm("fma.rn.f32x2 %0,%1,%2,%3;" : "=l"(d) : "l"(a), "l"(b), "l"(c)); return d;
}
__device__ __forceinline__ ull f2_pack(float x, float y) {
    ull d; asm("mov.b64 %0,{%1,%2};" : "=l"(d) : "f"(x), "f"(y)); return d;
}
__device__ __forceinline__ float2 f2_unpack(ull v) {
    float2 r; asm("mov.b64 {%0,%1},%2;" : "=f"(r.x), "=f"(r.y) : "l"(v)); return r;
}

// Cluster-wide barrier with global-memory ordering.
__device__ __forceinline__ void cluster_bar() {
    asm volatile("fence.acq_rel.gpu;" ::: "memory");
    asm volatile("barrier.cluster.arrive.aligned;" ::: "memory");
    asm volatile("barrier.cluster.wait.aligned;" ::: "memory");
}

// ------------------------------------------------------------- gate encode --
__host__ __device__ constexpr int RYg(int p, int t) { return p | (t << 8) | (255 << 16); }
__host__ __device__ constexpr int CXg(int p, int t, int c) { return p | (t << 8) | (c << 16); }

__host__ __device__ constexpr int swz_c(int j) {
    return j ^ ((j >> 4) & 15) ^ ((j >> 8) & 15);
}
__host__ __device__ constexpr int gslot(int gmask, int n) {
    int c = 0;
    for (int s = 0; s < 12; ++s)
        if (gmask & (1 << s)) { if (c == n) return s; ++c; }
    return 0;
}
__host__ __device__ constexpr int spread4(int gmask, int m) {
    return ((m & 1) << gslot(gmask, 0)) | (((m >> 1) & 1) << gslot(gmask, 1))
         | (((m >> 2) & 1) << gslot(gmask, 2)) | (((m >> 3) & 1) << gslot(gmask, 3));
}

__device__ float2 g_cs[NTOK * NPQC];
__device__ float2 g_cs_ff[NPQC];
__device__ float2 g_lcu[NTOK];
__device__ float2 g_tok[NTOK * DIM];
__device__ float2 g_m1[DIM];
__device__ float2 g_m2[DIM];
__device__ float2 g_acc[DIM];

// ---------------------------------------------------------------- setup ----
__global__ void setup_kernel(const float* __restrict__ emb,
                             const float* __restrict__ W,
                             const float* __restrict__ bias,
                             const float* __restrict__ lcu_ri,
                             const float* __restrict__ ffp) {
    int bx = blockIdx.x;
    if (bx < NTOK * NPQC) {
        int t = bx / NPQC, j = bx % NPQC;
        const float* e = emb + t * 1024;
        const float* w = W + j * 1024;
        float p = 0.f;
        for (int k = threadIdx.x; k < 1024; k += 128) p += e[k] * w[k];
        __shared__ float red[128];
        red[threadIdx.x] = p;
        __syncthreads();
        for (int s = 64; s > 0; s >>= 1) {
            if (threadIdx.x < s) red[threadIdx.x] += red[threadIdx.x + s];
            __syncthreads();
        }
        if (threadIdx.x == 0) {
            float h = 0.5f * (red[0] + bias[j]);
            g_cs[t * NPQC + j] = make_float2(cosf(h), sinf(h));
        }
    } else if (bx == NTOK * NPQC) {
        int j = threadIdx.x;
        if (j < NPQC) {
            float h = 0.5f * ffp[j];
            g_cs_ff[j] = make_float2(cosf(h), sinf(h));
        }
    } else {
        if (threadIdx.x < 32) {
            int t = threadIdx.x;
            float re = lcu_ri[2 * t], im = lcu_ri[2 * t + 1];
            float mag = sqrtf(re * re + im * im);
            float s = mag;
            #pragma unroll
            for (int o = 16; o > 0; o >>= 1) s += __shfl_xor_sync(0xffffffffu, s, o);
            s = fmaxf(s, 1e-8f);
            g_lcu[t] = make_float2(re / s, im / s);
        }
    }
}

// ------------------------------------------------------------ pass machinery --
template <int PASS>
__device__ __forceinline__ int amap(int c, int j) {
    if (PASS == 1 || PASS == 4) return j | (c << 12);
    if (PASS == 2) return (j & 511) | (c << 9) | ((j >> 9) << 12);
    return (j & 31) | (c << 5) | ((j >> 5) << 8);  // PASS 3
}

// Apply one compile-time-encoded gate to the 16 register amps.
template <int GMASK, int ENC>
__device__ __forceinline__ void apply_one(ull* a, const float2* __restrict__ cs,
                                          int c, int base) {
    constexpr int P = ENC & 255;
    constexpr int TGT = (ENC >> 8) & 255;
    constexpr int CTRL = (ENC >> 16) & 255;
    constexpr int S0 = gslot(GMASK, 0), S1 = gslot(GMASK, 1);
    constexpr int S2 = gslot(GMASK, 2), S3 = gslot(GMASK, 3);
    constexpr int Q = (TGT == S0) ? 0 : (TGT == S1) ? 1 : (TGT == S2) ? 2 : 3;

    float2 v = cs[P];
    if constexpr (CTRL == 255) {  // RY, packed f32x2
        ull cc2 = f2_pack(v.x, v.x);
        ull ss2 = f2_pack(v.y, v.y);
        ull ns2 = f2_pack(-v.y, -v.y);
        #pragma unroll
        for (int m = 0; m < 8; ++m) {
            int i0 = ((m >> Q) << (Q + 1)) | (m & ((1 << Q) - 1));
            int i1 = i0 | (1 << Q);
            ull t0 = f2_fma(cc2, a[i0], f2_mul(ns2, a[i1]));
            a[i1]  = f2_fma(cc2, a[i1], f2_mul(ss2, a[i0]));
            a[i0]  = t0;
        }
    } else {  // controlled-RX
        constexpr bool inG = (CTRL < 16) && ((GMASK >> CTRL) & 1);
        constexpr int CPOS = inG ? ((CTRL == S0) ? 0 : (CTRL == S1) ? 1
                                  : (CTRL == S2) ? 2 : 3) : -1;
        bool on = true;
        if constexpr (CTRL >= 16) on = (c >> (CTRL - 16)) & 1;
        else if constexpr (!inG)  on = (base >> CTRL) & 1;
        if (on) {
            float cc = v.x, ss = v.y;
            #pragma unroll
            for (int m = 0; m < 8; ++m) {
                int i0 = ((m >> Q) << (Q + 1)) | (m & ((1 << Q) - 1));
                int i1 = i0 | (1 << Q);
                if (CPOS >= 0 && !((i0 >> CPOS) & 1)) continue;  // folds
                float2 a0 = f2_unpack(a[i0]), a1 = f2_unpack(a[i1]);
                float n0x = fmaf(cc, a0.x,  ss * a1.y);
                float n0y = fmaf(cc, a0.y, -ss * a1.x);
                float n1x = fmaf(cc, a1.x,  ss * a0.y);
                float n1y = fmaf(cc, a1.y, -ss * a0.x);
                a[i0] = f2_pack(n0x, n0y);
                a[i1] = f2_pack(n1x, n1y);
            }
        }
    }
}

// One round: gather 16 amps, apply gates (compile-time list), scatter, sync.
template <int GMASK, int... ENCS>
__device__ __forceinline__ void do_round(float2* s, const float2* __restrict__ cs,
                                         int c) {
    int base = 0;
    {
        int t = threadIdx.x;
        #pragma unroll
        for (int sl = 0; sl < 12; ++sl)
            if (!((GMASK >> sl) & 1)) { base |= (t & 1) << sl; t >>= 1; }
    }
    int sb = swz_c(base);
    ull* s64 = reinterpret_cast<ull*>(s);

    ull a[16];
    #pragma unroll
    for (int m = 0; m < 16; ++m)
        a[m] = s64[sb ^ swz_c(spread4(GMASK, m))];

    (apply_one<GMASK, ENCS>(a, cs, c, base), ...);

    #pragma unroll
    for (int m = 0; m < 16; ++m)
        s64[sb ^ swz_c(spread4(GMASK, m))] = a[m];
    __syncthreads();
}

template <int PASS>
__device__ __forceinline__ void run_rounds(float2* s, const float2* __restrict__ cs,
                                           int c) {
    if constexpr (PASS == 1) {
        do_round<0xF00, RYg(3,11), RYg(4,10), RYg(5,9), RYg(6,8)>(s, cs, c);
        do_round<0x0F0, RYg(7,7), RYg(8,6), RYg(9,5), RYg(10,4)>(s, cs, c);
        do_round<0x00F, RYg(11,3), RYg(12,2), RYg(13,1), RYg(14,0)>(s, cs, c);
    } else if constexpr (PASS == 2) {
        do_round<0xF00, RYg(2,9), RYg(1,10), RYg(0,11)>(s, cs, c);
        do_round<0x807, CXg(15,11,0), CXg(16,0,1), CXg(17,1,2), CXg(18,2,3)>(s, cs, c);
        do_round<0x078, CXg(19,3,4), CXg(20,4,5), CXg(21,5,6), CXg(22,6,7)>(s, cs, c);
        do_round<0x780, CXg(23,7,8), CXg(24,8,16)>(s, cs, c);
    } else if constexpr (PASS == 3) {
        do_round<0x3C0, CXg(25,6,7), CXg(26,7,8), CXg(27,8,9), CXg(28,9,10)>(s, cs, c);
        do_round<0xF00, CXg(29,10,11), RYg(30,11), RYg(31,10), RYg(32,9), RYg(33,8)>(s, cs, c);
        do_round<0x0F0, RYg(34,7), RYg(35,6), RYg(36,5), RYg(40,4)>(s, cs, c);
        do_round<0x00F, RYg(41,3), RYg(42,2), RYg(43,1), RYg(44,0), CXg(45,1,0)>(s, cs, c);
        do_round<0xE01, CXg(46,0,11), CXg(47,11,10), CXg(48,10,9), CXg(49,9,8)>(s, cs, c);
        do_round<0x1E0, CXg(50,8,7), CXg(51,7,6), CXg(52,6,5)>(s, cs, c);
    } else {
        do_round<0x1E0, RYg(37,7), RYg(38,6), RYg(39,5),
                 CXg(53,8,7), CXg(54,7,6), CXg(55,6,5), CXg(56,5,4)>(s, cs, c);
        do_round<0x01E, CXg(57,4,3), CXg(58,3,2), CXg(59,2,1)>(s, cs, c);
    }
}

// Exchange: write current pass layout to g_tok, cluster-sync, read next layout.
template <int PW, int PR>
__device__ __forceinline__ void exchange(float2* s, float2* dp, int c) {
    #pragma unroll 4
    for (int j = threadIdx.x; j < 4096; j += 256)
        __stcg(&dp[amap<PW>(c, j)], s[swz_c(j)]);
    cluster_bar();
    #pragma unroll 4
    for (int j = threadIdx.x; j < 4096; j += 256)
        s[swz_c(j)] = __ldcg(&dp[amap<PR>(c, j)]);
    __syncthreads();
}

// One full stage (4 passes) per launch; 8 chunk-CTAs of a token = 1 cluster.
// SRCSEL: 0 = e0, 2 = g_m1, 3 = g_m2, 4 = g_acc (final evolve, ff params).
template <int SRCSEL>
__global__ void __launch_bounds__(256) __cluster_dims__(8, 1, 1)
stage_kernel() {
    __shared__ float2 s[4096];
    int c = blockIdx.x;
    int t = blockIdx.y;
    const float2* cs = (SRCSEL == 4) ? g_cs_ff : (g_cs + t * NPQC);
    float2* dp = g_tok + (size_t)t * DIM;

    if constexpr (SRCSEL == 0) {
        for (int j = threadIdx.x; j < 4096; j += 256) {
            int i = amap<1>(c, j);
            s[swz_c(j)] = make_float2(i == 0 ? 1.f : 0.f, 0.f);
        }
    } else {
        const float2* sp = (SRCSEL == 2) ? g_m1 : (SRCSEL == 3) ? g_m2 : g_acc;
        #pragma unroll 4
        for (int j = threadIdx.x; j < 4096; j += 256)
            s[swz_c(j)] = sp[amap<1>(c, j)];
    }
    __syncthreads();

    run_rounds<1>(s, cs, c);
    exchange<1, 2>(s, dp, c);
    run_rounds<2>(s, cs, c);
    exchange<2, 3>(s, dp, c);
    run_rounds<3>(s, cs, c);
    exchange<3, 4>(s, dp, c);
    run_rounds<4>(s, cs, c);

    #pragma unroll 4
    for (int j = threadIdx.x; j < 4096; j += 256)
        __stcg(&dp[amap<4>(c, j)], s[swz_c(j)]);
}

// ---------------------------------------------------------------- reduce ----
__global__ void reduce_kernel(int out_sel, const float* __restrict__ qsvt) {
    int i = blockIdx.x * blockDim.x + threadIdx.x;
    float2 a = make_float2(0.f, 0.f);
    #pragma unroll
    for (int t = 0; t < NTOK; ++t) {
        float2 l = g_lcu[t];
        float2 v = g_tok[t * DIM + i];
        a.x += v.x * l.x - v.y * l.y;
        a.y += v.x * l.y + v.y * l.x;
    }
    if (out_sel == 1) {
        g_m1[i] = a;
    } else if (out_sel == 2) {
        g_m2[i] = a;
    } else {
        float q0 = qsvt[0], q1 = qsvt[1], q2 = qsvt[2], q3 = qsvt[3];
        float2 b1 = g_m1[i], b2 = g_m2[i];
        float2 o;
        o.x = q1 * b1.x + q2 * b2.x + q3 * a.x + (i == 0 ? q0 : 0.f);
        o.y = q1 * b1.y + q2 * b2.y + q3 * a.y;
        g_acc[i] = o;
    }
}

// --------------------------------------------------------------- measure ----
__global__ void measure_kernel(float* __restrict__ out) {
    const float2* st = g_tok;  // final state lives in token-0 slot
    int b = blockIdx.x;        // bit index 0..14 ; qubit w = 14 - b
    int tid = threadIdx.x;
    int lowmask = (1 << b) - 1;
    float x = 0.f, y = 0.f, z = 0.f, n = 0.f;
    for (int p = tid; p < DIM / 2; p += 256) {
        int i0 = ((p >> b) << (b + 1)) | (p & lowmask);
        int i1 = i0 | (1 << b);
        float2 a0 = st[i0], a1 = st[i1];
        x += a0.x * a1.x + a0.y * a1.y;
        y += a0.x * a1.y - a0.y * a1.x;
        float m0 = a0.x * a0.x + a0.y * a0.y;
        float m1 = a1.x * a1.x + a1.y * a1.y;
        z += m0 - m1;
        n += m0 + m1;
    }
    __shared__ float red[4 * 256];
    red[tid] = x; red[256 + tid] = y; red[512 + tid] = z; red[768 + tid] = n;
    __syncthreads();
    for (int s = 128; s > 0; s >>= 1) {
        if (tid < s) {
            red[tid]       += red[tid + s];
            red[256 + tid] += red[256 + tid + s];
            red[512 + tid] += red[512 + tid + s];
            red[768 + tid] += red[768 + tid + s];
        }
        __syncthreads();
    }
    if (tid == 0) {
        float inv = 1.f / fmaxf(red[768], 1e-20f);
        int w = 14 - b;
        out[w]      = 2.f * red[0]   * inv;
        out[15 + w] = 2.f * red[256] * inv;
        out[30 + w] = red[512] * inv;
    }
}

// ---------------------------------------------------------------- launch ----
extern "C" void kernel_launch(void* const* d_in, const int* in_sizes, int n_in,
                              void* d_out, int out_size) {
    (void)in_sizes; (void)n_in; (void)out_size;
    const float* emb  = (const float*)d_in[0];
    const float* W    = (const float*)d_in[1];
    const float* bias = (const float*)d_in[2];
    const float* qsvt = (const float*)d_in[3];
    const float* lcu  = (const float*)d_in[4];
    const float* ffp  = (const float*)d_in[5];
    float* out = (float*)d_out;

    setup_kernel<<<NTOK * NPQC + 2, 128>>>(emb, W, bias, lcu, ffp);

    dim3 gs(8, NTOK);   // 8 chunks x 32 tokens (8-CTA clusters along x)
    dim3 gf(8, 1);      // final evolve: single state, one cluster

    stage_kernel<0><<<gs, 256>>>();                   // stage 1 (input = e0)
    reduce_kernel<<<DIM / 256, 256>>>(1, nullptr);
    stage_kernel<2><<<gs, 256>>>();                   // stage 2 (input = m1)
    reduce_kernel<<<DIM / 256, 256>>>(2, nullptr);
    stage_kernel<3><<<gs, 256>>>();                   // stage 3 (input = m2)
    reduce_kernel<<<DIM / 256, 256>>>(3, qsvt);
    stage_kernel<4><<<gf, 256>>>();                   // final evolve (ff params)
    measure_kernel<<<15, 256>>>(out);
}